// round 1
// baseline (speedup 1.0000x reference)
#include <cuda_runtime.h>
#include <math.h>
#include <stdint.h>

#define BW 64
#define BO 64
#define TW 32
#define TO 36
#define DD 512
#define STRIDE 516              // padded smem row stride (floats), 16B aligned
#define SCALE 0.044194173824159216f  // 1/sqrt(512)

__device__ float g_logits[BW * TW * BO];   // [wb][t][ob]
__device__ float g_partial[BW];

// packed f32x2 FMA (sm_100+): d = a*b + d elementwise on (lo,hi)
__device__ __forceinline__ void fma2(unsigned long long &d,
                                     unsigned long long a,
                                     unsigned long long b) {
    asm("fma.rn.f32x2 %0, %1, %2, %0;" : "+l"(d) : "l"(a), "l"(b));
}

union F4U { float4 f; unsigned long long u[2]; float s[4]; };
union U2F { unsigned long long u; float2 f; };

__device__ __forceinline__ float hsum2(unsigned long long a) {
    U2F t; t.u = a; return t.f.x + t.f.y;
}

extern __shared__ float smem[];

__global__ __launch_bounds__(288, 1)
void cap_main(const float* __restrict__ g_o,
              const float* __restrict__ g_u,
              const float* __restrict__ g_w,
              float* __restrict__ out_att,
              float* __restrict__ out_avo)
{
    const int ob  = blockIdx.x;
    const int wb  = blockIdx.y;
    const int tid = threadIdx.x;

    float*  w_s    = smem;                       // 32*516
    float*  u_s    = w_s + TW * STRIDE;          // 36*516 (u tile, later o tile)
    float2* att2   = (float2*)(u_s + TO * STRIDE); // 32*36 duplicated pairs
    float*  pmax   = (float*)(att2 + TW * TO);   // 288
    float*  psum   = pmax + 288;                 // 288
    float*  rowmax = psum + 288;                 // 32
    float*  rowinv = rowmax + 32;                // 32
    float*  lgp    = rowinv + 32;                // 32*18

    // ---------------- phase 1: load w tile (32x512) and u tile (36x512) ----
    for (int idx = tid; idx < TW * 128; idx += 288) {
        int t = idx >> 7, d4 = idx & 127;
        float4 v = reinterpret_cast<const float4*>(g_w)[(wb * TW + t) * 128 + d4];
        *reinterpret_cast<float4*>(&w_s[t * STRIDE + 4 * d4]) = v;
    }
    for (int idx = tid; idx < TO * 128; idx += 288) {
        int o = idx >> 7, d4 = idx & 127;
        float4 v = reinterpret_cast<const float4*>(g_u)[(ob * TO + o) * 128 + d4];
        *reinterpret_cast<float4*>(&u_s[o * STRIDE + 4 * d4]) = v;
    }
    __syncthreads();

    // ---------------- phase 2: scores (2t x 2o per thread, f32x2 over d) ---
    {
        const int tp = tid / 18, oq = tid % 18;
        const int t0 = 2 * tp, t1 = t0 + 1;
        const int o0 = oq, o1 = oq + 18;     // o1 offset 18 rows: spreads banks

        const float4* wr0 = reinterpret_cast<const float4*>(&w_s[t0 * STRIDE]);
        const float4* wr1 = reinterpret_cast<const float4*>(&w_s[t1 * STRIDE]);
        const float4* ur0 = reinterpret_cast<const float4*>(&u_s[o0 * STRIDE]);
        const float4* ur1 = reinterpret_cast<const float4*>(&u_s[o1 * STRIDE]);

        unsigned long long a00 = 0, a01 = 0, a10 = 0, a11 = 0;
        #pragma unroll 8
        for (int d4 = 0; d4 < 128; d4++) {
            F4U w0; w0.f = wr0[d4];
            F4U w1; w1.f = wr1[d4];
            F4U x0; x0.f = ur0[d4];
            F4U x1; x1.f = ur1[d4];
            fma2(a00, w0.u[0], x0.u[0]); fma2(a00, w0.u[1], x0.u[1]);
            fma2(a01, w0.u[0], x1.u[0]); fma2(a01, w0.u[1], x1.u[1]);
            fma2(a10, w1.u[0], x0.u[0]); fma2(a10, w1.u[1], x0.u[1]);
            fma2(a11, w1.u[0], x1.u[0]); fma2(a11, w1.u[1], x1.u[1]);
        }
        float s00 = hsum2(a00) * SCALE;
        float s01 = hsum2(a01) * SCALE;
        float s10 = hsum2(a10) * SCALE;
        float s11 = hsum2(a11) * SCALE;
        att2[t0 * TO + o0] = make_float2(s00, s00);
        att2[t0 * TO + o1] = make_float2(s01, s01);
        att2[t1 * TO + o0] = make_float2(s10, s10);
        att2[t1 * TO + o1] = make_float2(s11, s11);
    }
    __syncthreads();

    // ---------------- phase 3: softmax over To=36 per (t) row --------------
    const int st = tid / 9, sj = tid % 9;   // 32 rows x 9 threads, 4 o each
    float sc0, sc1, sc2, sc3, e0, e1, e2, e3;
    {
        int base = st * TO + 4 * sj;
        sc0 = att2[base + 0].x;
        sc1 = att2[base + 1].x;
        sc2 = att2[base + 2].x;
        sc3 = att2[base + 3].x;
        pmax[tid] = fmaxf(fmaxf(sc0, sc1), fmaxf(sc2, sc3));
    }
    __syncthreads();
    if (tid < 32) {
        float m = pmax[tid * 9];
        #pragma unroll
        for (int k = 1; k < 9; k++) m = fmaxf(m, pmax[tid * 9 + k]);
        rowmax[tid] = m;
    }
    __syncthreads();
    {
        float m = rowmax[st];
        e0 = expf(sc0 - m); e1 = expf(sc1 - m);
        e2 = expf(sc2 - m); e3 = expf(sc3 - m);
        psum[tid] = e0 + e1 + e2 + e3;
    }
    __syncthreads();
    if (tid < 32) {
        float s = 0.f;
        #pragma unroll
        for (int k = 0; k < 9; k++) s += psum[tid * 9 + k];
        rowinv[tid] = 1.f / s;
    }
    __syncthreads();
    {
        float inv = rowinv[st];
        float a0 = e0 * inv, a1 = e1 * inv, a2 = e2 * inv, a3 = e3 * inv;
        int base = st * TO + 4 * sj;
        att2[base + 0] = make_float2(a0, a0);
        att2[base + 1] = make_float2(a1, a1);
        att2[base + 2] = make_float2(a2, a2);
        att2[base + 3] = make_float2(a3, a3);
        // global att write (scalar: region base may be 4B-misaligned)
        int gb = ((wb * BO + ob) * TW + st) * TO + 4 * sj;
        out_att[gb + 0] = a0; out_att[gb + 1] = a1;
        out_att[gb + 2] = a2; out_att[gb + 3] = a3;
    }
    __syncthreads();

    // ---------------- phase 4a: load o tile over u_s ------------------------
    for (int idx = tid; idx < TO * 128; idx += 288) {
        int o = idx >> 7, d4 = idx & 127;
        float4 v = reinterpret_cast<const float4*>(g_o)[(ob * TO + o) * 128 + d4];
        *reinterpret_cast<float4*>(&u_s[o * STRIDE + 4 * d4]) = v;
    }
    __syncthreads();

    // ---------------- phase 4b: att_V_o = att @ o, logits fused -------------
    {
        const int tp = tid / 18, j2 = tid % 18;
        const int t0 = 2 * tp, t1 = t0 + 1;
        const float4* wr0 = reinterpret_cast<const float4*>(&w_s[t0 * STRIDE]);
        const float4* wr1 = reinterpret_cast<const float4*>(&w_s[t1 * STRIDE]);
        const unsigned long long* at0 =
            reinterpret_cast<const unsigned long long*>(att2 + t0 * TO);
        const unsigned long long* at1 =
            reinterpret_cast<const unsigned long long*>(att2 + t1 * TO);
        const int ob0 = (((wb * BO + ob) * TW + t0) * DD);
        const int ob1 = (((wb * BO + ob) * TW + t1) * DD);

        float lg0 = 0.f, lg1 = 0.f;
        for (int d4 = j2; d4 < 128; d4 += 18) {
            unsigned long long a00 = 0, a01 = 0, a10 = 0, a11 = 0;
            #pragma unroll
            for (int o = 0; o < TO; o++) {
                F4U ov; ov.f = *reinterpret_cast<const float4*>(&u_s[o * STRIDE + 4 * d4]);
                unsigned long long aa0 = at0[o];
                unsigned long long aa1 = at1[o];
                fma2(a00, aa0, ov.u[0]); fma2(a01, aa0, ov.u[1]);
                fma2(a10, aa1, ov.u[0]); fma2(a11, aa1, ov.u[1]);
            }
            F4U av0; av0.u[0] = a00; av0.u[1] = a01;
            F4U av1; av1.u[0] = a10; av1.u[1] = a11;
            F4U wv0; wv0.f = wr0[d4];
            F4U wv1; wv1.f = wr1[d4];
            lg0 += av0.s[0] * wv0.s[0] + av0.s[1] * wv0.s[1]
                 + av0.s[2] * wv0.s[2] + av0.s[3] * wv0.s[3];
            lg1 += av1.s[0] * wv1.s[0] + av1.s[1] * wv1.s[1]
                 + av1.s[2] * wv1.s[2] + av1.s[3] * wv1.s[3];
            // scalar stores: region base may be 4B-misaligned
            int p0 = ob0 + 4 * d4, p1 = ob1 + 4 * d4;
            out_avo[p0 + 0] = av0.s[0]; out_avo[p0 + 1] = av0.s[1];
            out_avo[p0 + 2] = av0.s[2]; out_avo[p0 + 3] = av0.s[3];
            out_avo[p1 + 0] = av1.s[0]; out_avo[p1 + 1] = av1.s[1];
            out_avo[p1 + 2] = av1.s[2]; out_avo[p1 + 3] = av1.s[3];
        }
        lgp[t0 * 18 + j2] = lg0;
        lgp[t1 * 18 + j2] = lg1;
    }
    __syncthreads();
    if (tid < 32) {
        float s = 0.f;
        #pragma unroll
        for (int k = 0; k < 18; k++) s += lgp[tid * 18 + k];
        g_logits[(wb * TW + tid) * BO + ob] = s;
    }
}

// log-softmax over Bo + masked diagonal accumulation, one block per wb
__global__ void cap_loss1(const int* __restrict__ g_mask)
{
    const int wb   = blockIdx.x;
    const int wid  = threadIdx.x >> 5;
    const int lane = threadIdx.x & 31;
    __shared__ float warp_part[8];

    float keepl = 1.f - (float)g_mask[wb * TW + lane];
    float nk = keepl;
    #pragma unroll
    for (int s = 16; s; s >>= 1) nk += __shfl_xor_sync(0xffffffffu, nk, s);

    float acc = 0.f;
    #pragma unroll
    for (int k = 0; k < 4; k++) {
        int t = wid + 8 * k;
        const float* row = g_logits + (wb * TW + t) * BO;
        float v0 = row[lane], v1 = row[lane + 32];
        float m = fmaxf(v0, v1);
        #pragma unroll
        for (int s = 16; s; s >>= 1) m = fmaxf(m, __shfl_xor_sync(0xffffffffu, m, s));
        float e = expf(v0 - m) + expf(v1 - m);
        #pragma unroll
        for (int s = 16; s; s >>= 1) e += __shfl_xor_sync(0xffffffffu, e, s);
        float lse = m + logf(e);
        float dv = (wb < 32) ? __shfl_sync(0xffffffffu, v0, wb)
                             : __shfl_sync(0xffffffffu, v1, wb - 32);
        float kt = 1.f - (float)g_mask[wb * TW + t];
        acc += kt * (dv - lse);
    }
    if (lane == 0) warp_part[wid] = acc;
    __syncthreads();
    if (threadIdx.x == 0) {
        float s = 0.f;
        #pragma unroll
        for (int k = 0; k < 8; k++) s += warp_part[k];
        g_partial[wb] = s / (nk + 1e-6f);
    }
}

__global__ void cap_loss2(float* __restrict__ out)
{
    __shared__ float sh[64];
    sh[threadIdx.x] = g_partial[threadIdx.x];
    __syncthreads();
    if (threadIdx.x == 0) {
        float s = 0.f;
        #pragma unroll
        for (int k = 0; k < 64; k++) s += sh[k];
        out[0] = -s / 64.f;
    }
}

extern "C" void kernel_launch(void* const* d_in, const int* in_sizes, int n_in,
                              void* d_out, int out_size)
{
    const float* g_o    = (const float*)d_in[0];
    const float* g_u    = (const float*)d_in[1];
    const float* g_w    = (const float*)d_in[2];
    const int*   g_mask = (const int*)d_in[3];

    float* out     = (float*)d_out;
    float* out_att = out + 1;                                    // loss first
    float* out_avo = out_att + (size_t)BW * BO * TW * TO;        // then att

    const size_t SMEM_BYTES = 154432;  // see layout in cap_main
    cudaFuncSetAttribute(cap_main, cudaFuncAttributeMaxDynamicSharedMemorySize,
                         (int)SMEM_BYTES);

    dim3 grid(BO, BW);
    cap_main<<<grid, 288, SMEM_BYTES>>>(g_o, g_u, g_w, out_att, out_avo);
    cap_loss1<<<BW, 256>>>(g_mask);
    cap_loss2<<<1, 64>>>(out);
}

// round 2
// speedup vs baseline: 1.1284x; 1.1284x over previous
#include <cuda_runtime.h>
#include <math.h>
#include <stdint.h>

#define BW 64
#define BO 64
#define TW 32
#define TO 36
#define DD 512
#define SCALE 0.044194173824159216f  // 1/sqrt(512)
#define OSTR 516                     // shifted o-tile row stride (floats)

// smem layout (float offsets)
#define OFF_W    0          // 32*512        = 16384
#define OFF_UO   16384      // max(36*512, 36*516+4) -> 18592
#define OFF_PART 34976      // 4*1184        = 4736
#define OFF_ATT2 39712      // 1152 float2   = 2304 floats
#define OFF_ATTC 42016      // 1168
#define OFF_LGP  43184      // 32*36 = 1152
#define OFF_LGP2 44336      // 128
#define OFF_PMAX 44464      // 288
#define OFF_PSUM 44752      // 288
#define OFF_RMAX 45040      // 32
#define OFF_RINV 45072      // 32
#define SMEM_FLOATS 45104   // 180416 bytes

#define SWZ(t) ((((t) ^ ((t) >> 2))) & 7)

__device__ float g_logits[BW * TW * BO];   // [wb][t][ob]
__device__ float g_partial[BW];

__device__ __forceinline__ void fma2(unsigned long long &d,
                                     unsigned long long a,
                                     unsigned long long b) {
    asm("fma.rn.f32x2 %0, %1, %2, %0;" : "+l"(d) : "l"(a), "l"(b));
}

union F4U { float4 f; unsigned long long u[2]; float s[4]; };
union U2F { unsigned long long u; float2 f; };

__device__ __forceinline__ float hsum2(unsigned long long a) {
    U2F t; t.u = a; return t.f.x + t.f.y;
}

extern __shared__ float smem[];

__global__ __launch_bounds__(288, 1)
void cap_main(const float* __restrict__ g_o,
              const float* __restrict__ g_u,
              const float* __restrict__ g_w,
              float* __restrict__ out_att,   // = d_out + 1
              float* __restrict__ out_avo)   // = d_out + 1 + 64*64*32*36
{
    const int ob  = blockIdx.x;
    const int wb  = blockIdx.y;
    const int blk = wb * BO + ob;
    const int tid = threadIdx.x;

    float*  w_s    = smem + OFF_W;
    float*  uo     = smem + OFF_UO;
    float*  part   = smem + OFF_PART;
    float2* att2   = (float2*)(smem + OFF_ATT2);
    const unsigned long long* att2u = (const unsigned long long*)(smem + OFF_ATT2);
    float*  att_cs = smem + OFF_ATTC;
    float*  lgp    = smem + OFF_LGP;
    float*  lgp2   = smem + OFF_LGP2;
    float*  pmax   = smem + OFF_PMAX;
    float*  psum   = smem + OFF_PSUM;
    float*  rowmax = smem + OFF_RMAX;
    float*  rowinv = smem + OFF_RINV;

    // ---------- phase 1: load w (32x512) and u (36x512), XOR-swizzled -------
    for (int idx = tid; idx < TW * 128; idx += 288) {
        int t = idx >> 7, c = idx & 127;
        float4 v = reinterpret_cast<const float4*>(g_w)[((size_t)wb * TW + t) * 128 + c];
        *reinterpret_cast<float4*>(&w_s[t * 512 + 4 * (c ^ SWZ(t))]) = v;
    }
    for (int idx = tid; idx < TO * 128; idx += 288) {
        int o = idx >> 7, c = idx & 127;
        float4 v = reinterpret_cast<const float4*>(g_u)[((size_t)ob * TO + o) * 128 + c];
        *reinterpret_cast<float4*>(&uo[o * 512 + 4 * (c ^ SWZ(o))]) = v;
    }
    __syncthreads();

    // ---------- phase 2: scores, 4t x 4o tile, 4-way d-split ----------------
    {
        const int dq = tid / 72;           // d-quarter (0..3)
        const int r  = tid % 72;
        const int tg = r & 7;              // t-group (0..7) -> t = 4*tg+i
        const int og = r >> 3;             // o-group (0..8) -> o = 4*og+j

        int swzT[4], swzO[4];
        const float* wb_[4];
        const float* ub_[4];
        #pragma unroll
        for (int i = 0; i < 4; i++) {
            int t = 4 * tg + i; swzT[i] = SWZ(t); wb_[i] = &w_s[t * 512];
            int o = 4 * og + i; swzO[i] = SWZ(o); ub_[i] = &uo[o * 512];
        }

        unsigned long long acc[4][4];
        #pragma unroll
        for (int i = 0; i < 4; i++)
            #pragma unroll
            for (int j = 0; j < 4; j++) acc[i][j] = 0ULL;

        const int c0 = dq * 32;
        #pragma unroll 4
        for (int cc = 0; cc < 32; cc++) {
            const int c = c0 + cc;
            F4U wv[4], uv[4];
            #pragma unroll
            for (int i = 0; i < 4; i++)
                wv[i].f = *reinterpret_cast<const float4*>(&wb_[i][4 * (c ^ swzT[i])]);
            #pragma unroll
            for (int j = 0; j < 4; j++)
                uv[j].f = *reinterpret_cast<const float4*>(&ub_[j][4 * (c ^ swzO[j])]);
            #pragma unroll
            for (int i = 0; i < 4; i++)
                #pragma unroll
                for (int j = 0; j < 4; j++) {
                    fma2(acc[i][j], wv[i].u[0], uv[j].u[0]);
                    fma2(acc[i][j], wv[i].u[1], uv[j].u[1]);
                }
        }
        #pragma unroll
        for (int i = 0; i < 4; i++)
            #pragma unroll
            for (int j = 0; j < 4; j++)
                part[dq * 1184 + (4 * tg + i) * 37 + (4 * og + j)] = hsum2(acc[i][j]);
    }
    __syncthreads();

    // ---------- phase 3: reduce d-quarters + softmax over To=36 -------------
    const int st = tid / 9, sj = tid % 9;      // row st, 4 o's per thread
    float sc[4], ee[4];
    {
        #pragma unroll
        for (int q = 0; q < 4; q++) {
            int o = 4 * sj + q;
            float s = 0.f;
            #pragma unroll
            for (int dq = 0; dq < 4; dq++) s += part[dq * 1184 + st * 37 + o];
            sc[q] = s * SCALE;
        }
        pmax[tid] = fmaxf(fmaxf(sc[0], sc[1]), fmaxf(sc[2], sc[3]));
    }
    __syncthreads();
    if (tid < 32) {
        float m = pmax[tid * 9];
        #pragma unroll
        for (int k = 1; k < 9; k++) m = fmaxf(m, pmax[tid * 9 + k]);
        rowmax[tid] = m;
    }
    __syncthreads();
    {
        float m = rowmax[st];
        float s = 0.f;
        #pragma unroll
        for (int q = 0; q < 4; q++) { ee[q] = expf(sc[q] - m); s += ee[q]; }
        psum[tid] = s;
    }
    __syncthreads();
    if (tid < 32) {
        float s = 0.f;
        #pragma unroll
        for (int k = 0; k < 9; k++) s += psum[tid * 9 + k];
        rowinv[tid] = 1.f / s;
    }
    __syncthreads();
    {
        float inv = rowinv[st];
        #pragma unroll
        for (int q = 0; q < 4; q++) {
            float a = ee[q] * inv;
            int idx = st * TO + 4 * sj + q;
            att2[idx]       = make_float2(a, a);
            att_cs[1 + idx] = a;
        }
    }
    __syncthreads();

    // ---------- att store (shifted float4) + phase 4a: o tile (shift +1) ----
    {
        const size_t ab = (size_t)blk * (TW * TO);
        if (tid < 287) {
            float4 v = *reinterpret_cast<const float4*>(&att_cs[4 + 4 * tid]);
            *reinterpret_cast<float4*>(&out_att[ab + 3 + 4 * tid]) = v;
        } else if (tid == 287) {
            out_att[ab + 0]    = att_cs[1];
            out_att[ab + 1]    = att_cs[2];
            out_att[ab + 2]    = att_cs[3];
            out_att[ab + 1151] = att_cs[1152];
        }
    }
    for (int task = tid; task < TO * 127; task += 288) {
        int o = task / 127, k = task % 127;
        const float* gr = g_o + ((size_t)ob * TO + o) * 512;
        float4 A  = *reinterpret_cast<const float4*>(&gr[4 * k]);
        float4 Bv = *reinterpret_cast<const float4*>(&gr[4 * k + 4]);
        *reinterpret_cast<float4*>(&uo[o * OSTR + 4 + 4 * k]) =
            make_float4(A.w, Bv.x, Bv.y, Bv.z);
    }
    if (tid < 144) {
        int o = tid / 4, e = tid % 4;
        const float* gr = g_o + ((size_t)ob * TO + o) * 512;
        if (e < 3) uo[o * OSTR + 1 + e] = gr[e];
        else       uo[o * OSTR + 512]   = gr[511];
    }
    __syncthreads();

    // ---------- phase 4b: att_V_o (4t x 4d windows), logits fused -----------
    {
        const int tg4 = tid / 36;          // 0..7 -> t = 4*tg4+i
        const int jj  = tid % 36;          // window group
        float lg[4] = {0.f, 0.f, 0.f, 0.f};

        #pragma unroll
        for (int m = 0; m < 4; m++) {
            int k = jj + 36 * m;
            if (k < 127) {
                unsigned long long a[4][2];
                #pragma unroll
                for (int i = 0; i < 4; i++) { a[i][0] = 0ULL; a[i][1] = 0ULL; }
                const float* ow = &uo[4 + 4 * k];
                #pragma unroll 4
                for (int o = 0; o < TO; o++) {
                    F4U ov; ov.f = *reinterpret_cast<const float4*>(&ow[o * OSTR]);
                    #pragma unroll
                    for (int i = 0; i < 4; i++) {
                        unsigned long long aa = att2u[(tg4 * 4 + i) * TO + o];
                        fma2(a[i][0], aa, ov.u[0]);
                        fma2(a[i][1], aa, ov.u[1]);
                    }
                }
                #pragma unroll
                for (int i = 0; i < 4; i++) {
                    int t = tg4 * 4 + i;
                    F4U av; av.u[0] = a[i][0]; av.u[1] = a[i][1];
                    *reinterpret_cast<float4*>(
                        &out_avo[((size_t)blk * TW + t) * DD + 3 + 4 * k]) = av.f;
                    int s = SWZ(t);
                    F4U wA; wA.f = *reinterpret_cast<const float4*>(&w_s[t * 512 + 4 * (k ^ s)]);
                    F4U wB; wB.f = *reinterpret_cast<const float4*>(&w_s[t * 512 + 4 * ((k + 1) ^ s)]);
                    lg[i] += av.s[0] * wA.s[3] + av.s[1] * wB.s[0]
                           + av.s[2] * wB.s[1] + av.s[3] * wB.s[2];
                }
            }
        }
        #pragma unroll
        for (int i = 0; i < 4; i++) lgp[(tg4 * 4 + i) * TO + jj] = lg[i];
    }
    // edge columns d in {0,1,2,511} for every t row
    if (tid < 128) {
        int t = tid / 4, e = tid % 4;
        int d    = (e < 3) ? e        : 511;
        int soff = (e < 3) ? (1 + e)  : 512;
        float acc = 0.f;
        #pragma unroll 4
        for (int o = 0; o < TO; o++)
            acc += att2[t * TO + o].x * uo[o * OSTR + soff];
        out_avo[((size_t)blk * TW + t) * DD + d] = acc;
        int s = SWZ(t);
        float wv = w_s[t * 512 + 4 * ((d >> 2) ^ s) + (d & 3)];
        lgp2[tid] = acc * wv;
    }
    __syncthreads();

    if (tid < 32) {
        float s = 0.f;
        #pragma unroll
        for (int k = 0; k < TO; k++) s += lgp[tid * TO + k];
        #pragma unroll
        for (int e = 0; e < 4; e++)  s += lgp2[tid * 4 + e];
        g_logits[(wb * TW + tid) * BO + ob] = s;
    }
}

// log-softmax over Bo + masked diagonal accumulation, one block per wb
__global__ void cap_loss1(const int* __restrict__ g_mask)
{
    const int wb   = blockIdx.x;
    const int wid  = threadIdx.x >> 5;
    const int lane = threadIdx.x & 31;
    __shared__ float warp_part[8];

    float keepl = 1.f - (float)g_mask[wb * TW + lane];
    float nk = keepl;
    #pragma unroll
    for (int s = 16; s; s >>= 1) nk += __shfl_xor_sync(0xffffffffu, nk, s);

    float acc = 0.f;
    #pragma unroll
    for (int k = 0; k < 4; k++) {
        int t = wid + 8 * k;
        const float* row = g_logits + (wb * TW + t) * BO;
        float v0 = row[lane], v1 = row[lane + 32];
        float m = fmaxf(v0, v1);
        #pragma unroll
        for (int s = 16; s; s >>= 1) m = fmaxf(m, __shfl_xor_sync(0xffffffffu, m, s));
        float e = expf(v0 - m) + expf(v1 - m);
        #pragma unroll
        for (int s = 16; s; s >>= 1) e += __shfl_xor_sync(0xffffffffu, e, s);
        float lse = m + logf(e);
        float dv = (wb < 32) ? __shfl_sync(0xffffffffu, v0, wb)
                             : __shfl_sync(0xffffffffu, v1, wb - 32);
        float kt = 1.f - (float)g_mask[wb * TW + t];
        acc += kt * (dv - lse);
    }
    if (lane == 0) warp_part[wid] = acc;
    __syncthreads();
    if (threadIdx.x == 0) {
        float s = 0.f;
        #pragma unroll
        for (int k = 0; k < 8; k++) s += warp_part[k];
        g_partial[wb] = s / (nk + 1e-6f);
    }
}

__global__ void cap_loss2(float* __restrict__ out)
{
    __shared__ float sh[64];
    sh[threadIdx.x] = g_partial[threadIdx.x];
    __syncthreads();
    if (threadIdx.x == 0) {
        float s = 0.f;
        #pragma unroll
        for (int k = 0; k < 64; k++) s += sh[k];
        out[0] = -s / 64.f;
    }
}

extern "C" void kernel_launch(void* const* d_in, const int* in_sizes, int n_in,
                              void* d_out, int out_size)
{
    const float* g_o    = (const float*)d_in[0];
    const float* g_u    = (const float*)d_in[1];
    const float* g_w    = (const float*)d_in[2];
    const int*   g_mask = (const int*)d_in[3];

    float* out     = (float*)d_out;
    float* out_att = out + 1;
    float* out_avo = out_att + (size_t)BW * BO * TW * TO;

    const size_t SMEM_BYTES = (size_t)SMEM_FLOATS * sizeof(float);
    cudaFuncSetAttribute(cap_main, cudaFuncAttributeMaxDynamicSharedMemorySize,
                         (int)SMEM_BYTES);

    dim3 grid(BO, BW);
    cap_main<<<grid, 288, SMEM_BYTES>>>(g_o, g_u, g_w, out_att, out_avo);
    cap_loss1<<<BW, 256>>>(g_mask);
    cap_loss2<<<1, 64>>>(out);
}

// round 3
// speedup vs baseline: 1.6051x; 1.4225x over previous
#include <cuda_runtime.h>
#include <math.h>
#include <stdint.h>

#define BW 64
#define BO 64
#define TW 32
#define TO 36
#define DD 512
#define SCALE 0.044194173824159216f  // 1/sqrt(512)
#define OSTR 516                     // shifted o-tile row stride (floats)
#define NTHR 576

// smem layout (float offsets)
#define OFF_W    0          // 32*512  = 16384
#define OFF_UO   16384      // 36*516+4 -> 18592
#define OFF_PART 34976      // 8*1184  = 9472
#define OFF_ATT2 44448      // 1152 float2 = 2304 floats
#define OFF_ATTC 46752      // 1168
#define OFF_LGP  47920      // 32*72 = 2304
#define OFF_LGP2 50224      // 128
#define OFF_PMAX 50352      // 288
#define OFF_PSUM 50640      // 288
#define OFF_RMAX 50928      // 32
#define OFF_RINV 50960      // 32
#define SMEM_FLOATS 50992   // 203968 bytes

#define SWZ(t) ((((t) ^ ((t) >> 2))) & 7)

__device__ float g_logits[BW * TW * BO];   // [wb][t][ob]
__device__ float g_partial[BW];

__device__ __forceinline__ void fma2(unsigned long long &d,
                                     unsigned long long a,
                                     unsigned long long b) {
    asm("fma.rn.f32x2 %0, %1, %2, %0;" : "+l"(d) : "l"(a), "l"(b));
}

union F4U { float4 f; unsigned long long u[2]; float s[4]; };
union U2F { unsigned long long u; float2 f; };

__device__ __forceinline__ float hsum2(unsigned long long a) {
    U2F t; t.u = a; return t.f.x + t.f.y;
}

extern __shared__ float smem[];

__global__ __launch_bounds__(NTHR, 1)
void cap_main(const float* __restrict__ g_o,
              const float* __restrict__ g_u,
              const float* __restrict__ g_w,
              float* __restrict__ out_att,   // = d_out + 1
              float* __restrict__ out_avo)   // = d_out + 1 + 64*64*32*36
{
    const int ob  = blockIdx.x;
    const int wb  = blockIdx.y;
    const int blk = wb * BO + ob;
    const int tid = threadIdx.x;

    float*  w_s    = smem + OFF_W;
    float*  uo     = smem + OFF_UO;
    float*  part   = smem + OFF_PART;
    float2* att2   = (float2*)(smem + OFF_ATT2);
    const unsigned long long* att2u = (const unsigned long long*)(smem + OFF_ATT2);
    float*  att_cs = smem + OFF_ATTC;
    float*  lgp    = smem + OFF_LGP;
    float*  lgp2   = smem + OFF_LGP2;
    float*  pmax   = smem + OFF_PMAX;
    float*  psum   = smem + OFF_PSUM;
    float*  rowmax = smem + OFF_RMAX;
    float*  rowinv = smem + OFF_RINV;

    // ---------- phase 1: load w (32x512) and u (36x512), XOR-swizzled -------
    for (int idx = tid; idx < TW * 128; idx += NTHR) {
        int t = idx >> 7, c = idx & 127;
        float4 v = reinterpret_cast<const float4*>(g_w)[((size_t)wb * TW + t) * 128 + c];
        *reinterpret_cast<float4*>(&w_s[t * 512 + 4 * (c ^ SWZ(t))]) = v;
    }
    for (int idx = tid; idx < TO * 128; idx += NTHR) {
        int o = idx >> 7, c = idx & 127;
        float4 v = reinterpret_cast<const float4*>(g_u)[((size_t)ob * TO + o) * 128 + c];
        *reinterpret_cast<float4*>(&uo[o * 512 + 4 * (c ^ SWZ(o))]) = v;
    }
    __syncthreads();

    // ---------- phase 2: scores, 4t x 4o tile, 8-way d-split ----------------
    {
        const int dq = tid / 72;           // d-eighth (0..7)
        const int r  = tid % 72;
        const int tg = r & 7;              // t = 4*tg+i
        const int og = r >> 3;             // o = 4*og+j (0..8)

        int swzT[4], swzO[4];
        const float* wb_[4];
        const float* ub_[4];
        #pragma unroll
        for (int i = 0; i < 4; i++) {
            int t = 4 * tg + i; swzT[i] = SWZ(t); wb_[i] = &w_s[t * 512];
            int o = 4 * og + i; swzO[i] = SWZ(o); ub_[i] = &uo[o * 512];
        }

        unsigned long long acc[4][4];
        #pragma unroll
        for (int i = 0; i < 4; i++)
            #pragma unroll
            for (int j = 0; j < 4; j++) acc[i][j] = 0ULL;

        const int c0 = dq * 16;
        #pragma unroll 4
        for (int cc = 0; cc < 16; cc++) {
            const int c = c0 + cc;
            F4U wv[4], uv[4];
            #pragma unroll
            for (int i = 0; i < 4; i++)
                wv[i].f = *reinterpret_cast<const float4*>(&wb_[i][4 * (c ^ swzT[i])]);
            #pragma unroll
            for (int j = 0; j < 4; j++)
                uv[j].f = *reinterpret_cast<const float4*>(&ub_[j][4 * (c ^ swzO[j])]);
            #pragma unroll
            for (int i = 0; i < 4; i++)
                #pragma unroll
                for (int j = 0; j < 4; j++) {
                    fma2(acc[i][j], wv[i].u[0], uv[j].u[0]);
                    fma2(acc[i][j], wv[i].u[1], uv[j].u[1]);
                }
        }
        #pragma unroll
        for (int i = 0; i < 4; i++)
            #pragma unroll
            for (int j = 0; j < 4; j++)
                part[dq * 1184 + (4 * tg + i) * 37 + (4 * og + j)] = hsum2(acc[i][j]);
    }
    __syncthreads();

    // ---------- phase 3: reduce d-slices + softmax over To=36 ---------------
    const int st = tid / 9, sj = tid % 9;      // valid for tid<288
    float sc[4], ee[4];
    if (tid < 288) {
        #pragma unroll
        for (int q = 0; q < 4; q++) {
            int o = 4 * sj + q;
            float s = 0.f;
            #pragma unroll
            for (int dq = 0; dq < 8; dq++) s += part[dq * 1184 + st * 37 + o];
            sc[q] = s * SCALE;
        }
        pmax[tid] = fmaxf(fmaxf(sc[0], sc[1]), fmaxf(sc[2], sc[3]));
    }
    __syncthreads();
    if (tid < 32) {
        float m = pmax[tid * 9];
        #pragma unroll
        for (int k = 1; k < 9; k++) m = fmaxf(m, pmax[tid * 9 + k]);
        rowmax[tid] = m;
    }
    __syncthreads();
    if (tid < 288) {
        float m = rowmax[st];
        float s = 0.f;
        #pragma unroll
        for (int q = 0; q < 4; q++) { ee[q] = expf(sc[q] - m); s += ee[q]; }
        psum[tid] = s;
    }
    __syncthreads();
    if (tid < 32) {
        float s = 0.f;
        #pragma unroll
        for (int k = 0; k < 9; k++) s += psum[tid * 9 + k];
        rowinv[tid] = 1.f / s;
    }
    __syncthreads();
    if (tid < 288) {
        float inv = rowinv[st];
        #pragma unroll
        for (int q = 0; q < 4; q++) {
            float a = ee[q] * inv;
            int idx = st * TO + 4 * sj + q;
            att2[idx]       = make_float2(a, a);
            att_cs[1 + idx] = a;
        }
    }
    __syncthreads();

    // ---------- att store (shifted float4) + phase 4a: o tile (shift +1) ----
    {
        const size_t ab = (size_t)blk * (TW * TO);
        if (tid < 287) {
            float4 v = *reinterpret_cast<const float4*>(&att_cs[4 + 4 * tid]);
            *reinterpret_cast<float4*>(&out_att[ab + 3 + 4 * tid]) = v;
        } else if (tid == 287) {
            out_att[ab + 0]    = att_cs[1];
            out_att[ab + 1]    = att_cs[2];
            out_att[ab + 2]    = att_cs[3];
            out_att[ab + 1151] = att_cs[1152];
        }
    }
    for (int task = tid; task < TO * 127; task += NTHR) {
        int o = task / 127, k = task % 127;
        const float* gr = g_o + ((size_t)ob * TO + o) * 512;
        float4 A  = *reinterpret_cast<const float4*>(&gr[4 * k]);
        float4 Bv = *reinterpret_cast<const float4*>(&gr[4 * k + 4]);
        *reinterpret_cast<float4*>(&uo[o * OSTR + 4 + 4 * k]) =
            make_float4(A.w, Bv.x, Bv.y, Bv.z);
    }
    if (tid < 144) {
        int o = tid / 4, e = tid % 4;
        const float* gr = g_o + ((size_t)ob * TO + o) * 512;
        if (e < 3) uo[o * OSTR + 1 + e] = gr[e];
        else       uo[o * OSTR + 512]   = gr[511];
    }
    __syncthreads();

    // ---------- phase 4b: att_V_o, o-outer, 2 windows/thread in registers ---
    {
        const int tg4 = tid / 72;          // t = 4*tg4 + i
        const int jj  = tid % 72;
        const bool have2 = (jj <= 54);     // k1 = jj+72 <= 126 valid
        const int k0 = jj;
        const int k1 = have2 ? (jj + 72) : 126;

        const float* ow0 = &uo[4 + 4 * k0];
        const float* ow1 = &uo[4 + 4 * k1];
        const unsigned long long* attp = att2u + (tg4 * 4) * TO;

        unsigned long long a0[4][2], a1[4][2];
        #pragma unroll
        for (int i = 0; i < 4; i++) {
            a0[i][0] = a0[i][1] = 0ULL;
            a1[i][0] = a1[i][1] = 0ULL;
        }

        #pragma unroll 4
        for (int o = 0; o < TO; o++) {
            unsigned long long aa[4];
            #pragma unroll
            for (int i = 0; i < 4; i++) aa[i] = attp[i * TO + o];
            F4U ov0; ov0.f = *reinterpret_cast<const float4*>(&ow0[o * OSTR]);
            F4U ov1; ov1.f = *reinterpret_cast<const float4*>(&ow1[o * OSTR]);
            #pragma unroll
            for (int i = 0; i < 4; i++) {
                fma2(a0[i][0], aa[i], ov0.u[0]);
                fma2(a0[i][1], aa[i], ov0.u[1]);
                fma2(a1[i][0], aa[i], ov1.u[0]);
                fma2(a1[i][1], aa[i], ov1.u[1]);
            }
        }

        #pragma unroll
        for (int i = 0; i < 4; i++) {
            const int t = 4 * tg4 + i;
            const int s = SWZ(t);
            const size_t tb = ((size_t)blk * TW + t) * DD;
            float lg;
            {
                F4U av; av.u[0] = a0[i][0]; av.u[1] = a0[i][1];
                *reinterpret_cast<float4*>(&out_avo[tb + 3 + 4 * k0]) = av.f;
                F4U wA; wA.f = *reinterpret_cast<const float4*>(&w_s[t * 512 + 4 * (k0 ^ s)]);
                F4U wB; wB.f = *reinterpret_cast<const float4*>(&w_s[t * 512 + 4 * ((k0 + 1) ^ s)]);
                lg = av.s[0] * wA.s[3] + av.s[1] * wB.s[0]
                   + av.s[2] * wB.s[1] + av.s[3] * wB.s[2];
            }
            if (have2) {
                F4U av; av.u[0] = a1[i][0]; av.u[1] = a1[i][1];
                *reinterpret_cast<float4*>(&out_avo[tb + 3 + 4 * k1]) = av.f;
                F4U wA; wA.f = *reinterpret_cast<const float4*>(&w_s[t * 512 + 4 * (k1 ^ s)]);
                F4U wB; wB.f = *reinterpret_cast<const float4*>(&w_s[t * 512 + 4 * ((k1 + 1) ^ s)]);
                lg += av.s[0] * wA.s[3] + av.s[1] * wB.s[0]
                    + av.s[2] * wB.s[1] + av.s[3] * wB.s[2];
            }
            lgp[t * 72 + jj] = lg;
        }
    }
    // edge columns d in {0,1,2,511} for every t row
    if (tid < 128) {
        int t = tid / 4, e = tid % 4;
        int d    = (e < 3) ? e        : 511;
        int soff = (e < 3) ? (1 + e)  : 512;
        float acc = 0.f;
        #pragma unroll 4
        for (int o = 0; o < TO; o++)
            acc += att2[t * TO + o].x * uo[o * OSTR + soff];
        out_avo[((size_t)blk * TW + t) * DD + d] = acc;
        int s = SWZ(t);
        float wv = w_s[t * 512 + 4 * ((d >> 2) ^ s) + (d & 3)];
        lgp2[tid] = acc * wv;
    }
    __syncthreads();

    if (tid < 32) {
        float s = 0.f;
        #pragma unroll
        for (int k = 0; k < 72; k++) s += lgp[tid * 72 + k];
        #pragma unroll
        for (int e = 0; e < 4; e++)  s += lgp2[tid * 4 + e];
        g_logits[(wb * TW + tid) * BO + ob] = s;
    }
}

// log-softmax over Bo + masked diagonal accumulation, one block per wb
__global__ void cap_loss1(const int* __restrict__ g_mask)
{
    const int wb   = blockIdx.x;
    const int wid  = threadIdx.x >> 5;
    const int lane = threadIdx.x & 31;
    __shared__ float warp_part[8];

    float keepl = 1.f - (float)g_mask[wb * TW + lane];
    float nk = keepl;
    #pragma unroll
    for (int s = 16; s; s >>= 1) nk += __shfl_xor_sync(0xffffffffu, nk, s);

    float acc = 0.f;
    #pragma unroll
    for (int k = 0; k < 4; k++) {
        int t = wid + 8 * k;
        const float* row = g_logits + (wb * TW + t) * BO;
        float v0 = row[lane], v1 = row[lane + 32];
        float m = fmaxf(v0, v1);
        #pragma unroll
        for (int s = 16; s; s >>= 1) m = fmaxf(m, __shfl_xor_sync(0xffffffffu, m, s));
        float e = expf(v0 - m) + expf(v1 - m);
        #pragma unroll
        for (int s = 16; s; s >>= 1) e += __shfl_xor_sync(0xffffffffu, e, s);
        float lse = m + logf(e);
        float dv = (wb < 32) ? __shfl_sync(0xffffffffu, v0, wb)
                             : __shfl_sync(0xffffffffu, v1, wb - 32);
        float kt = 1.f - (float)g_mask[wb * TW + t];
        acc += kt * (dv - lse);
    }
    if (lane == 0) warp_part[wid] = acc;
    __syncthreads();
    if (threadIdx.x == 0) {
        float s = 0.f;
        #pragma unroll
        for (int k = 0; k < 8; k++) s += warp_part[k];
        g_partial[wb] = s / (nk + 1e-6f);
    }
}

__global__ void cap_loss2(float* __restrict__ out)
{
    __shared__ float sh[64];
    sh[threadIdx.x] = g_partial[threadIdx.x];
    __syncthreads();
    if (threadIdx.x == 0) {
        float s = 0.f;
        #pragma unroll
        for (int k = 0; k < 64; k++) s += sh[k];
        out[0] = -s / 64.f;
    }
}

extern "C" void kernel_launch(void* const* d_in, const int* in_sizes, int n_in,
                              void* d_out, int out_size)
{
    const float* g_o    = (const float*)d_in[0];
    const float* g_u    = (const float*)d_in[1];
    const float* g_w    = (const float*)d_in[2];
    const int*   g_mask = (const int*)d_in[3];

    float* out     = (float*)d_out;
    float* out_att = out + 1;
    float* out_avo = out_att + (size_t)BW * BO * TW * TO;

    const size_t SMEM_BYTES = (size_t)SMEM_FLOATS * sizeof(float);
    cudaFuncSetAttribute(cap_main, cudaFuncAttributeMaxDynamicSharedMemorySize,
                         (int)SMEM_BYTES);

    dim3 grid(BO, BW);
    cap_main<<<grid, NTHR, SMEM_BYTES>>>(g_o, g_u, g_w, out_att, out_avo);
    cap_loss1<<<BW, 256>>>(g_mask);
    cap_loss2<<<1, 64>>>(out);
}

// round 4
// speedup vs baseline: 1.6236x; 1.0115x over previous
#include <cuda_runtime.h>
#include <math.h>
#include <stdint.h>

#define BW 64
#define BO 64
#define TW 32
#define TO 36
#define DD 512
#define SCALE 0.044194173824159216f  // 1/sqrt(512)
#define WSTR 520                     // w row stride (floats)
#define OSTR 516                     // u/o row stride (floats)
#define NTHR 576

// smem layout (float offsets)
#define OFF_W    0          // 32*520 = 16640
#define OFF_UO   16640      // 36*516+4 -> 18592
#define OFF_SCR  35232      // 32*37 = 1184
#define OFF_ATTC 36416      // 1168
#define OFF_LGP  37584      // 32*72 = 2304
#define OFF_LGP2 39888      // 128
#define OFF_PMAX 40016      // 288
#define OFF_PSUM 40304      // 288
#define OFF_RMAX 40592      // 32
#define OFF_RINV 40624      // 32
#define SMEM_FLOATS 40656   // 162624 bytes

__device__ float g_logits[BW * TW * BO];   // [wb][t][ob]
__device__ float g_partial[BW];

typedef unsigned long long ull;

__device__ __forceinline__ void fma2(ull &d, ull a, ull b) {
    asm("fma.rn.f32x2 %0, %1, %2, %0;" : "+l"(d) : "l"(a), "l"(b));
}
__device__ __forceinline__ ull pack2(float a) {
    ull r; asm("mov.b64 %0, {%1, %1};" : "=l"(r) : "f"(a)); return r;
}

union F4U { float4 f; ull u[2]; float s[4]; };
union U2F { ull u; float2 f; };

__device__ __forceinline__ float hsum2(ull a) {
    U2F t; t.u = a; return t.f.x + t.f.y;
}

extern __shared__ float smem[];

__global__ __launch_bounds__(NTHR, 1)
void cap_main(const float* __restrict__ g_o,
              const float* __restrict__ g_u,
              const float* __restrict__ g_w,
              float* __restrict__ out_att,   // = d_out + 1
              float* __restrict__ out_avo)   // = d_out + 1 + 64*64*32*36
{
    const int ob  = blockIdx.x;
    const int wb  = blockIdx.y;
    const int blk = wb * BO + ob;
    const int tid = threadIdx.x;

    float*  w_s    = smem + OFF_W;
    float*  uo     = smem + OFF_UO;
    float*  scr    = smem + OFF_SCR;
    float*  att_cs = smem + OFF_ATTC;
    float*  lgp    = smem + OFF_LGP;
    float*  lgp2   = smem + OFF_LGP2;
    float*  pmax   = smem + OFF_PMAX;
    float*  psum   = smem + OFF_PSUM;
    float*  rowmax = smem + OFF_RMAX;
    float*  rowinv = smem + OFF_RINV;

    // ---------- phase 1: load w (32x512, stride 520) and u (36x512, 516) ----
    for (int idx = tid; idx < TW * 128; idx += NTHR) {
        int t = idx >> 7, c = idx & 127;
        float4 v = reinterpret_cast<const float4*>(g_w)[((size_t)wb * TW + t) * 128 + c];
        *reinterpret_cast<float4*>(&w_s[t * WSTR + 4 * c]) = v;
    }
    for (int idx = tid; idx < TO * 128; idx += NTHR) {
        int o = idx >> 7, c = idx & 127;
        float4 v = reinterpret_cast<const float4*>(g_u)[((size_t)ob * TO + o) * 128 + c];
        *reinterpret_cast<float4*>(&uo[o * OSTR + 4 * c]) = v;
    }
    __syncthreads();

    // ---------- phase 2: scores, 8t x 4o tile, 16 d-slices in lane bits -----
    {
        const int dq  = tid & 15;          // d-slice (lane bits 0-3)
        const int grp = tid >> 4;          // 0..35
        const int tg  = grp & 3;           // t base = tg*8
        const int og  = grp >> 2;          // 0..8 -> o base = og*4

        const float* wbase = w_s + (tg * 8) * WSTR + 4 * dq;
        const float* ubase = uo  + (og * 4) * OSTR + 4 * dq;

        ull acc[8][4];
        #pragma unroll
        for (int i = 0; i < 8; i++)
            #pragma unroll
            for (int j = 0; j < 4; j++) acc[i][j] = 0ULL;

        #pragma unroll
        for (int cc = 0; cc < 8; cc++) {   // c = 16*cc + dq
            F4U uv[4];
            #pragma unroll
            for (int j = 0; j < 4; j++)
                uv[j].f = *reinterpret_cast<const float4*>(&ubase[j * OSTR + cc * 64]);
            #pragma unroll
            for (int i = 0; i < 8; i++) {
                F4U wv;
                wv.f = *reinterpret_cast<const float4*>(&wbase[i * WSTR + cc * 64]);
                #pragma unroll
                for (int j = 0; j < 4; j++) {
                    fma2(acc[i][j], wv.u[0], uv[j].u[0]);
                    fma2(acc[i][j], wv.u[1], uv[j].u[1]);
                }
            }
        }

        float sums[32];
        #pragma unroll
        for (int i = 0; i < 8; i++)
            #pragma unroll
            for (int j = 0; j < 4; j++) sums[i * 4 + j] = hsum2(acc[i][j]);

        #pragma unroll
        for (int s = 1; s < 16; s <<= 1)
            #pragma unroll
            for (int k = 0; k < 32; k++)
                sums[k] += __shfl_xor_sync(0xffffffffu, sums[k], s);

        // all 16 dq lanes now hold the full 32 sums; each stores 2
        #pragma unroll
        for (int e = 0; e < 2; e++) {
            int k = 2 * dq + e;
            int i = k >> 2, j = k & 3;
            scr[(tg * 8 + i) * 37 + og * 4 + j] = sums[k];
        }
    }
    __syncthreads();

    // ---------- phase 3: softmax over To=36 per t row -----------------------
    const int st = tid / 9, sj = tid % 9;      // valid for tid<288
    float sc[4], ee[4];
    if (tid < 288) {
        #pragma unroll
        for (int q = 0; q < 4; q++)
            sc[q] = scr[st * 37 + 4 * sj + q] * SCALE;
        pmax[tid] = fmaxf(fmaxf(sc[0], sc[1]), fmaxf(sc[2], sc[3]));
    }
    __syncthreads();
    if (tid < 32) {
        float m = pmax[tid * 9];
        #pragma unroll
        for (int k = 1; k < 9; k++) m = fmaxf(m, pmax[tid * 9 + k]);
        rowmax[tid] = m;
    }
    __syncthreads();
    if (tid < 288) {
        float m = rowmax[st];
        float s = 0.f;
        #pragma unroll
        for (int q = 0; q < 4; q++) { ee[q] = expf(sc[q] - m); s += ee[q]; }
        psum[tid] = s;
    }
    __syncthreads();
    if (tid < 32) {
        float s = 0.f;
        #pragma unroll
        for (int k = 0; k < 9; k++) s += psum[tid * 9 + k];
        rowinv[tid] = 1.f / s;
    }
    __syncthreads();
    if (tid < 288) {
        float inv = rowinv[st];
        #pragma unroll
        for (int q = 0; q < 4; q++)
            att_cs[1 + st * TO + 4 * sj + q] = ee[q] * inv;
    }
    __syncthreads();

    // ---------- att store (shifted float4) + phase 4a: o tile (shift +1) ----
    {
        const size_t ab = (size_t)blk * (TW * TO);
        if (tid < 287) {
            float4 v = *reinterpret_cast<const float4*>(&att_cs[4 + 4 * tid]);
            *reinterpret_cast<float4*>(&out_att[ab + 3 + 4 * tid]) = v;
        } else if (tid == 287) {
            out_att[ab + 0]    = att_cs[1];
            out_att[ab + 1]    = att_cs[2];
            out_att[ab + 2]    = att_cs[3];
            out_att[ab + 1151] = att_cs[1152];
        }
    }
    for (int task = tid; task < TO * 127; task += NTHR) {
        int o = task / 127, k = task % 127;
        const float* gr = g_o + ((size_t)ob * TO + o) * 512;
        float4 A  = *reinterpret_cast<const float4*>(&gr[4 * k]);
        float4 Bv = *reinterpret_cast<const float4*>(&gr[4 * k + 4]);
        *reinterpret_cast<float4*>(&uo[o * OSTR + 4 + 4 * k]) =
            make_float4(A.w, Bv.x, Bv.y, Bv.z);
    }
    if (tid < 144) {
        int o = tid / 4, e = tid % 4;
        const float* gr = g_o + ((size_t)ob * TO + o) * 512;
        if (e < 3) uo[o * OSTR + 1 + e] = gr[e];
        else       uo[o * OSTR + 512]   = gr[511];
    }
    __syncthreads();

    // ---------- phase 4b: att_V_o, o-outer, scalar att + in-reg pack --------
    {
        const int tg4 = tid / 72;          // t = 4*tg4 + i
        const int jj  = tid % 72;
        const bool have2 = (jj <= 54);     // k1 = jj+72 <= 126 valid
        const int k0 = jj;
        const int k1 = have2 ? (jj + 72) : 126;

        const float* ow0 = &uo[4 + 4 * k0];
        const float* ow1 = &uo[4 + 4 * k1];
        const float* attp = att_cs + 1 + (tg4 * 4) * TO;

        ull a0[4][2], a1[4][2];
        #pragma unroll
        for (int i = 0; i < 4; i++) {
            a0[i][0] = a0[i][1] = 0ULL;
            a1[i][0] = a1[i][1] = 0ULL;
        }

        #pragma unroll 4
        for (int o = 0; o < TO; o++) {
            F4U ov0; ov0.f = *reinterpret_cast<const float4*>(&ow0[o * OSTR]);
            F4U ov1; ov1.f = *reinterpret_cast<const float4*>(&ow1[o * OSTR]);
            #pragma unroll
            for (int i = 0; i < 4; i++) {
                ull aa = pack2(attp[i * TO + o]);
                fma2(a0[i][0], aa, ov0.u[0]);
                fma2(a0[i][1], aa, ov0.u[1]);
                fma2(a1[i][0], aa, ov1.u[0]);
                fma2(a1[i][1], aa, ov1.u[1]);
            }
        }

        #pragma unroll
        for (int i = 0; i < 4; i++) {
            const int t = 4 * tg4 + i;
            const size_t tb = ((size_t)blk * TW + t) * DD;
            float lg;
            {
                F4U av; av.u[0] = a0[i][0]; av.u[1] = a0[i][1];
                *reinterpret_cast<float4*>(&out_avo[tb + 3 + 4 * k0]) = av.f;
                F4U wA; wA.f = *reinterpret_cast<const float4*>(&w_s[t * WSTR + 4 * k0]);
                F4U wB; wB.f = *reinterpret_cast<const float4*>(&w_s[t * WSTR + 4 * k0 + 4]);
                lg = av.s[0] * wA.s[3] + av.s[1] * wB.s[0]
                   + av.s[2] * wB.s[1] + av.s[3] * wB.s[2];
            }
            if (have2) {
                F4U av; av.u[0] = a1[i][0]; av.u[1] = a1[i][1];
                *reinterpret_cast<float4*>(&out_avo[tb + 3 + 4 * k1]) = av.f;
                F4U wA; wA.f = *reinterpret_cast<const float4*>(&w_s[t * WSTR + 4 * k1]);
                F4U wB; wB.f = *reinterpret_cast<const float4*>(&w_s[t * WSTR + 4 * k1 + 4]);
                lg += av.s[0] * wA.s[3] + av.s[1] * wB.s[0]
                    + av.s[2] * wB.s[1] + av.s[3] * wB.s[2];
            }
            lgp[t * 72 + jj] = lg;
        }
    }
    // edge columns d in {0,1,2,511} for every t row
    if (tid < 128) {
        int t = tid / 4, e = tid % 4;
        int d    = (e < 3) ? e        : 511;
        int soff = (e < 3) ? (1 + e)  : 512;
        float acc = 0.f;
        #pragma unroll 4
        for (int o = 0; o < TO; o++)
            acc += att_cs[1 + t * TO + o] * uo[o * OSTR + soff];
        out_avo[((size_t)blk * TW + t) * DD + d] = acc;
        lgp2[tid] = acc * w_s[t * WSTR + d];
    }
    __syncthreads();

    if (tid < 32) {
        float s = 0.f;
        #pragma unroll
        for (int k = 0; k < 72; k++) s += lgp[tid * 72 + k];
        #pragma unroll
        for (int e = 0; e < 4; e++)  s += lgp2[tid * 4 + e];
        g_logits[(wb * TW + tid) * BO + ob] = s;
    }
}

// log-softmax over Bo + masked diagonal accumulation, one block per wb
__global__ void cap_loss1(const int* __restrict__ g_mask)
{
    const int wb   = blockIdx.x;
    const int wid  = threadIdx.x >> 5;
    const int lane = threadIdx.x & 31;
    __shared__ float warp_part[8];

    float keepl = 1.f - (float)g_mask[wb * TW + lane];
    float nk = keepl;
    #pragma unroll
    for (int s = 16; s; s >>= 1) nk += __shfl_xor_sync(0xffffffffu, nk, s);

    float acc = 0.f;
    #pragma unroll
    for (int k = 0; k < 4; k++) {
        int t = wid + 8 * k;
        const float* row = g_logits + (wb * TW + t) * BO;
        float v0 = row[lane], v1 = row[lane + 32];
        float m = fmaxf(v0, v1);
        #pragma unroll
        for (int s = 16; s; s >>= 1) m = fmaxf(m, __shfl_xor_sync(0xffffffffu, m, s));
        float e = expf(v0 - m) + expf(v1 - m);
        #pragma unroll
        for (int s = 16; s; s >>= 1) e += __shfl_xor_sync(0xffffffffu, e, s);
        float lse = m + logf(e);
        float dv = (wb < 32) ? __shfl_sync(0xffffffffu, v0, wb)
                             : __shfl_sync(0xffffffffu, v1, wb - 32);
        float kt = 1.f - (float)g_mask[wb * TW + t];
        acc += kt * (dv - lse);
    }
    if (lane == 0) warp_part[wid] = acc;
    __syncthreads();
    if (threadIdx.x == 0) {
        float s = 0.f;
        #pragma unroll
        for (int k = 0; k < 8; k++) s += warp_part[k];
        g_partial[wb] = s / (nk + 1e-6f);
    }
}

__global__ void cap_loss2(float* __restrict__ out)
{
    __shared__ float sh[64];
    sh[threadIdx.x] = g_partial[threadIdx.x];
    __syncthreads();
    if (threadIdx.x == 0) {
        float s = 0.f;
        #pragma unroll
        for (int k = 0; k < 64; k++) s += sh[k];
        out[0] = -s / 64.f;
    }
}

extern "C" void kernel_launch(void* const* d_in, const int* in_sizes, int n_in,
                              void* d_out, int out_size)
{
    const float* g_o    = (const float*)d_in[0];
    const float* g_u    = (const float*)d_in[1];
    const float* g_w    = (const float*)d_in[2];
    const int*   g_mask = (const int*)d_in[3];

    float* out     = (float*)d_out;
    float* out_att = out + 1;
    float* out_avo = out_att + (size_t)BW * BO * TW * TO;

    const size_t SMEM_BYTES = (size_t)SMEM_FLOATS * sizeof(float);
    cudaFuncSetAttribute(cap_main, cudaFuncAttributeMaxDynamicSharedMemorySize,
                         (int)SMEM_BYTES);

    dim3 grid(BO, BW);
    cap_main<<<grid, NTHR, SMEM_BYTES>>>(g_o, g_u, g_w, out_att, out_avo);
    cap_loss1<<<BW, 256>>>(g_mask);
    cap_loss2<<<1, 64>>>(out);
}